// round 2
// baseline (speedup 1.0000x reference)
#include <cuda_runtime.h>
#include <math.h>

// ---------------- problem constants (fixed dataset) ----------------
#define MAX_N 20000
#define MAX_E 320000
#define NGRAPH 32

// ---------------- scratch (static device memory; no allocs) --------
__device__ float g_bufA[MAX_N * 1024];
__device__ float g_bufB[MAX_N * 1024];
__device__ float g_bufC[MAX_N * 1024];
__device__ float g_es[MAX_N * 4];
__device__ float g_ed[MAX_N * 4];
__device__ int   g_deg[MAX_N];
__device__ int   g_off[MAX_N + 1];
__device__ int   g_cur[MAX_N];
__device__ int   g_srcidx[MAX_E];
__device__ int   g_gcnt[NGRAPH];
__device__ int   g_goff[NGRAPH];
__device__ float g_pooled[NGRAPH * 768];

// ---------------- helpers ----------------
__device__ __forceinline__ float lrelu(float x) { return x > 0.f ? x : 0.2f * x; }
__device__ __forceinline__ float elu(float x)   { return x > 0.f ? x : expm1f(x); }

// ---------------- SGEMM: C[M,N] = A[M,K] @ B[K,N]  (+bias, +ELU) ----------------
// 128x128 tile, BK=8, 256 threads, 8x8 per thread (2x2 quadrants of 4).
// Requires K % 8 == 0 and N % 128 == 0 (true for all uses here).
template<int ACT>  // 0 = none, 1 = ELU
__global__ void __launch_bounds__(256) sgemm128(
    const float* __restrict__ A, const float* __restrict__ B,
    const float* __restrict__ bias, float* __restrict__ C,
    int M, int N, int K)
{
    __shared__ float As[8][128];
    __shared__ float Bs[8][128];

    const int tid = threadIdx.x;
    const int tx = tid & 15;   // 0..15
    const int ty = tid >> 4;   // 0..15
    const int row0 = blockIdx.y * 128;
    const int col0 = blockIdx.x * 128;

    float acc[8][8];
#pragma unroll
    for (int i = 0; i < 8; i++)
#pragma unroll
        for (int j = 0; j < 8; j++) acc[i][j] = 0.f;

    const int aRow = tid >> 1;          // 0..127
    const int aCol = (tid & 1) * 4;     // 0 or 4
    const int bRow = tid >> 5;          // 0..7
    const int bCol = (tid & 31) * 4;    // 0..124

    for (int k0 = 0; k0 < K; k0 += 8) {
        float4 av = make_float4(0.f, 0.f, 0.f, 0.f);
        int gr = row0 + aRow;
        if (gr < M) av = *(const float4*)&A[(size_t)gr * K + k0 + aCol];
        As[aCol + 0][aRow] = av.x;
        As[aCol + 1][aRow] = av.y;
        As[aCol + 2][aRow] = av.z;
        As[aCol + 3][aRow] = av.w;

        float4 bv = *(const float4*)&B[(size_t)(k0 + bRow) * N + col0 + bCol];
        *(float4*)&Bs[bRow][bCol] = bv;
        __syncthreads();

#pragma unroll
        for (int kk = 0; kk < 8; kk++) {
            float4 a0 = *(const float4*)&As[kk][ty * 4];
            float4 a1 = *(const float4*)&As[kk][64 + ty * 4];
            float4 b0 = *(const float4*)&Bs[kk][tx * 4];
            float4 b1 = *(const float4*)&Bs[kk][64 + tx * 4];
            float a[8] = {a0.x, a0.y, a0.z, a0.w, a1.x, a1.y, a1.z, a1.w};
            float b[8] = {b0.x, b0.y, b0.z, b0.w, b1.x, b1.y, b1.z, b1.w};
#pragma unroll
            for (int i = 0; i < 8; i++)
#pragma unroll
                for (int j = 0; j < 8; j++)
                    acc[i][j] = fmaf(a[i], b[j], acc[i][j]);
        }
        __syncthreads();
    }

#pragma unroll
    for (int ih = 0; ih < 2; ih++) {
#pragma unroll
        for (int i = 0; i < 4; i++) {
            int r = row0 + ih * 64 + ty * 4 + i;
            if (r >= M) continue;
#pragma unroll
            for (int jh = 0; jh < 2; jh++) {
                int c = col0 + jh * 64 + tx * 4;
                float4 v;
                v.x = acc[ih * 4 + i][jh * 4 + 0];
                v.y = acc[ih * 4 + i][jh * 4 + 1];
                v.z = acc[ih * 4 + i][jh * 4 + 2];
                v.w = acc[ih * 4 + i][jh * 4 + 3];
                if (bias) {
                    float4 bb = *(const float4*)&bias[c];
                    v.x += bb.x; v.y += bb.y; v.z += bb.z; v.w += bb.w;
                }
                if (ACT == 1) {
                    v.x = elu(v.x); v.y = elu(v.y); v.z = elu(v.z); v.w = elu(v.w);
                }
                *(float4*)&C[(size_t)r * N + c] = v;
            }
        }
    }
}

// ---------------- attention score projections ----------------
// es[n][h] = dot(hW[n, h*256 : h*256+256], a_src[h]); same for ed.
template<int H>
__global__ void att_scores(const float* __restrict__ hW,
                           const float* __restrict__ a_src,
                           const float* __restrict__ a_dst,
                           int n)
{
    int warp = (blockIdx.x * blockDim.x + threadIdx.x) >> 5;
    int lane = threadIdx.x & 31;
    if (warp >= n * H) return;
    int node = warp / H, h = warp - node * H;
    const float* row = hW + (size_t)node * (H * 256) + h * 256;
    float ss = 0.f, sd = 0.f;
#pragma unroll
    for (int c = lane; c < 256; c += 32) {
        float v = row[c];
        ss = fmaf(v, a_src[h * 256 + c], ss);
        sd = fmaf(v, a_dst[h * 256 + c], sd);
    }
#pragma unroll
    for (int o = 16; o; o >>= 1) {
        ss += __shfl_xor_sync(0xFFFFFFFFu, ss, o);
        sd += __shfl_xor_sync(0xFFFFFFFFu, sd, o);
    }
    if (!lane) { g_es[node * H + h] = ss; g_ed[node * H + h] = sd; }
}

// ---------------- CSR construction ----------------
__global__ void zero_counts(int n) {
    int i = blockIdx.x * blockDim.x + threadIdx.x;
    if (i < n) g_deg[i] = 0;
    if (i < NGRAPH) g_gcnt[i] = 0;
}

__global__ void count_deg(const int* __restrict__ ei, int E) {
    int i = blockIdx.x * blockDim.x + threadIdx.x;
    if (i < E) atomicAdd(&g_deg[ei[E + i]], 1);   // dst row
}

__global__ void count_graphs(const int* __restrict__ batch, int n) {
    int i = blockIdx.x * blockDim.x + threadIdx.x;
    if (i < n) atomicAdd(&g_gcnt[batch[i]], 1);
}

__global__ void scan_deg(int n) {
    __shared__ int part[1024];
    int tid = threadIdx.x;
    int per = (n + 1023) >> 10;
    int base = tid * per;
    int s = 0;
    for (int k = 0; k < per; k++) { int idx = base + k; if (idx < n) s += g_deg[idx]; }
    part[tid] = s;
    __syncthreads();
    for (int o = 1; o < 1024; o <<= 1) {
        int v = (tid >= o) ? part[tid - o] : 0;
        __syncthreads();
        part[tid] += v;
        __syncthreads();
    }
    int run = (tid == 0) ? 0 : part[tid - 1];
    for (int k = 0; k < per; k++) {
        int idx = base + k;
        if (idx < n) { g_off[idx] = run; g_cur[idx] = run; run += g_deg[idx]; }
    }
    if (tid == 0) g_off[n] = part[1023];
}

__global__ void graph_offsets() {
    if (threadIdx.x == 0) {
        int r = 0;
        for (int g = 0; g < NGRAPH; g++) { g_goff[g] = r; r += g_gcnt[g]; }
    }
}

__global__ void fill_csr(const int* __restrict__ ei, int E) {
    int i = blockIdx.x * blockDim.x + threadIdx.x;
    if (i < E) {
        int d = ei[E + i];
        int p = atomicAdd(&g_cur[d], 1);
        g_srcidx[p] = ei[i];
    }
}

// ---------------- fused GAT aggregation + bias + LayerNorm + ELU (+residual) ----
// One CTA per destination node. CT = H*256 columns, CT/4 threads (float4/thread).
template<int H, bool RES>
__global__ void gat_agg(const float* __restrict__ hW,
                        const float* __restrict__ bias,
                        const float* __restrict__ lng,
                        const float* __restrict__ lnb,
                        const float* __restrict__ resid,
                        float* __restrict__ out)
{
    constexpr int CT = H * 256;
    constexpr int NT = CT / 4;
    const int i = blockIdx.x;
    const int tid = threadIdx.x;
    const int c0 = tid * 4;
    const int head = c0 >> 8;
    const int start = g_off[i], end = g_off[i + 1];

    float edv[H], selfl[H];
#pragma unroll
    for (int h = 0; h < H; h++) {
        edv[h] = g_ed[i * H + h];
        selfl[h] = lrelu(g_es[i * H + h] + edv[h]);
    }

    // pass 1: per-head max over incoming edges (+ self-loop)
    float mx[H];
#pragma unroll
    for (int h = 0; h < H; h++) mx[h] = selfl[h];
    for (int e = start + tid; e < end; e += NT) {
        int s = g_srcidx[e];
#pragma unroll
        for (int h = 0; h < H; h++) {
            float l = lrelu(g_es[s * H + h] + edv[h]);
            mx[h] = fmaxf(mx[h], l);
        }
    }
    __shared__ float red[NT];
#pragma unroll
    for (int h = 0; h < H; h++) {
        red[tid] = mx[h];
        __syncthreads();
        for (int o = NT / 2; o; o >>= 1) {
            if (tid < o) red[tid] = fmaxf(red[tid], red[tid + o]);
            __syncthreads();
        }
        mx[h] = red[0];
        __syncthreads();
    }

    // pass 2: denominator
    float part[H];
#pragma unroll
    for (int h = 0; h < H; h++) part[h] = 0.f;
    for (int e = start + tid; e < end; e += NT) {
        int s = g_srcidx[e];
#pragma unroll
        for (int h = 0; h < H; h++) {
            float l = lrelu(g_es[s * H + h] + edv[h]);
            part[h] += __expf(l - mx[h]);
        }
    }
    float den[H];
#pragma unroll
    for (int h = 0; h < H; h++) {
        red[tid] = part[h];
        __syncthreads();
        for (int o = NT / 2; o; o >>= 1) {
            if (tid < o) red[tid] += red[tid + o];
            __syncthreads();
        }
        den[h] = red[0] + __expf(selfl[h] - mx[h]);
        __syncthreads();
    }

    // pass 3: weighted gather-accumulate over edges (all threads see all edges)
    const float m_h = mx[head];
    const float inv = 1.f / (den[head] + 1e-16f);
    const float edh = edv[head];
    float4 acc = make_float4(0.f, 0.f, 0.f, 0.f);
    for (int e = start; e < end; e++) {
        int s = g_srcidx[e];
        float l = lrelu(g_es[s * H + head] + edh);
        float a = __expf(l - m_h) * inv;
        float4 v = *(const float4*)&hW[(size_t)s * CT + c0];
        acc.x = fmaf(a, v.x, acc.x);
        acc.y = fmaf(a, v.y, acc.y);
        acc.z = fmaf(a, v.z, acc.z);
        acc.w = fmaf(a, v.w, acc.w);
    }
    {   // self-loop
        float a = __expf(selfl[head] - m_h) * inv;
        float4 v = *(const float4*)&hW[(size_t)i * CT + c0];
        acc.x = fmaf(a, v.x, acc.x);
        acc.y = fmaf(a, v.y, acc.y);
        acc.z = fmaf(a, v.z, acc.z);
        acc.w = fmaf(a, v.w, acc.w);
    }
    {   // bias
        float4 b = *(const float4*)&bias[c0];
        acc.x += b.x; acc.y += b.y; acc.z += b.z; acc.w += b.w;
    }

    // LayerNorm over the row (row is distributed across the block)
    float s1 = acc.x + acc.y + acc.z + acc.w;
    float s2 = acc.x * acc.x + acc.y * acc.y + acc.z * acc.z + acc.w * acc.w;
    red[tid] = s1; __syncthreads();
    for (int o = NT / 2; o; o >>= 1) { if (tid < o) red[tid] += red[tid + o]; __syncthreads(); }
    float S1 = red[0]; __syncthreads();
    red[tid] = s2; __syncthreads();
    for (int o = NT / 2; o; o >>= 1) { if (tid < o) red[tid] += red[tid + o]; __syncthreads(); }
    float S2 = red[0];

    float mu = S1 / (float)CT;
    float var = S2 / (float)CT - mu * mu;
    float rstd = rsqrtf(var + 1e-5f);
    float4 gv = *(const float4*)&lng[c0];
    float4 bv = *(const float4*)&lnb[c0];
    float o0 = elu((acc.x - mu) * rstd * gv.x + bv.x);
    float o1 = elu((acc.y - mu) * rstd * gv.y + bv.y);
    float o2 = elu((acc.z - mu) * rstd * gv.z + bv.z);
    float o3 = elu((acc.w - mu) * rstd * gv.w + bv.w);
    if (RES) {
        float4 rv = *(const float4*)&resid[(size_t)i * CT + c0];
        o0 += rv.x; o1 += rv.y; o2 += rv.z; o3 += rv.w;
    }
    float4 ov = make_float4(o0, o1, o2, o3);
    *(float4*)&out[(size_t)i * CT + c0] = ov;
}

// ---------------- per-graph pooling: mean | max | sum ----------------
__global__ void pool_kernel(const float* __restrict__ x3) {
    int g = blockIdx.x;
    int tid = threadIdx.x;   // 256 threads, one column each
    int s = g_goff[g], cnt = g_gcnt[g];
    float sum = 0.f, mx = -INFINITY;
    for (int k = 0; k < cnt; k++) {
        float v = x3[(size_t)(s + k) * 256 + tid];
        sum += v;
        mx = fmaxf(mx, v);
    }
    float mean = sum / fmaxf((float)cnt, 1.f);
    g_pooled[g * 768 + tid] = mean;
    g_pooled[g * 768 + 256 + tid] = mx;
    g_pooled[g * 768 + 512 + tid] = sum;
}

// ---------------- classifier head ----------------
__global__ void classify(const float* __restrict__ w1, const float* __restrict__ b1,
                         const float* __restrict__ w2, const float* __restrict__ b2,
                         float* __restrict__ outv)
{
    int g = blockIdx.x;
    int j = threadIdx.x;  // 128
    float s = b1[j];
    for (int k = 0; k < 768; k++)
        s = fmaf(g_pooled[g * 768 + k], w1[k * 128 + j], s);
    s = fmaxf(s, 0.f);
    float t = s * w2[j];
    __shared__ float red[128];
    red[j] = t; __syncthreads();
    for (int o = 64; o; o >>= 1) { if (j < o) red[j] += red[j + o]; __syncthreads(); }
    if (!j) outv[g] = red[0] + b2[0];
}

// ---------------- launch ----------------
extern "C" void kernel_launch(void* const* d_in, const int* in_sizes, int n_in,
                              void* d_out, int out_size)
{
    const float* x        = (const float*)d_in[0];
    const int*   ei       = (const int*)d_in[1];
    const int*   batch    = (const int*)d_in[2];
    const float* proj_w   = (const float*)d_in[3];
    const float* proj_b   = (const float*)d_in[4];
    const float* gat1_w   = (const float*)d_in[5];
    const float* att1_src = (const float*)d_in[6];
    const float* att1_dst = (const float*)d_in[7];
    const float* gat1_b   = (const float*)d_in[8];
    const float* ln1_g    = (const float*)d_in[9];
    const float* ln1_b    = (const float*)d_in[10];
    const float* gat2_w   = (const float*)d_in[11];
    const float* att2_src = (const float*)d_in[12];
    const float* att2_dst = (const float*)d_in[13];
    const float* gat2_b   = (const float*)d_in[14];
    const float* ln2_g    = (const float*)d_in[15];
    const float* ln2_b    = (const float*)d_in[16];
    const float* gat3_w   = (const float*)d_in[17];
    const float* att3_src = (const float*)d_in[18];
    const float* att3_dst = (const float*)d_in[19];
    const float* gat3_b   = (const float*)d_in[20];
    const float* ln3_g    = (const float*)d_in[21];
    const float* ln3_b    = (const float*)d_in[22];
    const float* cls1_w   = (const float*)d_in[23];
    const float* cls1_b   = (const float*)d_in[24];
    const float* cls2_w   = (const float*)d_in[25];
    const float* cls2_b   = (const float*)d_in[26];

    const int N = in_sizes[0] / 768;
    const int E = in_sizes[1] / 2;
    const int G = out_size;

    float* bufA; cudaGetSymbolAddress((void**)&bufA, g_bufA);
    float* bufB; cudaGetSymbolAddress((void**)&bufB, g_bufB);
    float* bufC; cudaGetSymbolAddress((void**)&bufC, g_bufC);

    // CSR + graph segmentation (shared across all 3 GAT layers)
    zero_counts<<<(N + 255) / 256, 256>>>(N);
    count_deg<<<(E + 255) / 256, 256>>>(ei, E);
    count_graphs<<<(N + 255) / 256, 256>>>(batch, N);
    scan_deg<<<1, 1024>>>(N);
    graph_offsets<<<1, 32>>>();
    fill_csr<<<(E + 255) / 256, 256>>>(ei, E);

    dim3 blk(256);

    // proj: h = elu(x @ proj_w + b)  -> bufA [N,768]
    sgemm128<1><<<dim3(768 / 128, (N + 127) / 128), blk>>>(x, proj_w, proj_b, bufA, N, 768, 768);

    // ---- GAT layer 1 ----
    sgemm128<0><<<dim3(1024 / 128, (N + 127) / 128), blk>>>(bufA, gat1_w, nullptr, bufB, N, 1024, 768);
    att_scores<4><<<(N * 4 + 7) / 8, 256>>>(bufB, att1_src, att1_dst, N);
    gat_agg<4, false><<<N, 256>>>(bufB, gat1_b, ln1_g, ln1_b, nullptr, bufC);   // bufC = x1

    // ---- GAT layer 2 ----
    sgemm128<0><<<dim3(1024 / 128, (N + 127) / 128), blk>>>(bufC, gat2_w, nullptr, bufB, N, 1024, 1024);
    att_scores<4><<<(N * 4 + 7) / 8, 256>>>(bufB, att2_src, att2_dst, N);
    gat_agg<4, true><<<N, 256>>>(bufB, gat2_b, ln2_g, ln2_b, bufC, bufA);       // bufA = x2

    // ---- GAT layer 3 ----
    sgemm128<0><<<dim3(256 / 128, (N + 127) / 128), blk>>>(bufA, gat3_w, nullptr, bufB, N, 256, 1024);
    att_scores<1><<<(N + 7) / 8, 256>>>(bufB, att3_src, att3_dst, N);
    gat_agg<1, false><<<N, 64>>>(bufB, gat3_b, ln3_g, ln3_b, nullptr, bufC);    // bufC = x3

    // ---- pooling + classifier ----
    pool_kernel<<<G, 256>>>(bufC);
    classify<<<G, 128>>>(cls1_w, cls1_b, cls2_w, cls2_b, (float*)d_out);
}

// round 12
// speedup vs baseline: 1.7298x; 1.7298x over previous
#include <cuda_runtime.h>
#include <cuda_bf16.h>
#include <math.h>
#include <stdint.h>

// ---------------- problem constants (fixed dataset) ----------------
#define MAX_N 20000
#define MAX_E 320000
#define NGRAPH 32

// ---------------- scratch (static device memory; no allocs) --------
__device__ float g_bufA[MAX_N * 1024];
__device__ float g_bufB[MAX_N * 1024];
__device__ float g_bufC[MAX_N * 1024];
__device__ float g_es[MAX_N * 4];
__device__ float g_ed[MAX_N * 4];
__device__ int   g_deg[MAX_N];
__device__ int   g_off[MAX_N + 1];
__device__ int   g_cur[MAX_N];
__device__ int   g_srcidx[MAX_E];
__device__ int   g_gcnt[NGRAPH];
__device__ int   g_goff[NGRAPH];
__device__ float g_pooled[NGRAPH * 768];
// bf16 hi/lo activation slots (double-rounded split), stride = feature dim
__device__ __nv_bfloat16 g_h0[MAX_N * 1024], g_l0[MAX_N * 1024];
__device__ __nv_bfloat16 g_h1[MAX_N * 1024], g_l1[MAX_N * 1024];
// bf16 hi/lo transposed weights, [N,K] K-major
__device__ __nv_bfloat16 g_wPh[768 * 768],   g_wPl[768 * 768];
__device__ __nv_bfloat16 g_w1h[1024 * 768],  g_w1l[1024 * 768];
__device__ __nv_bfloat16 g_w2h[1024 * 1024], g_w2l[1024 * 1024];
__device__ __nv_bfloat16 g_w3h[256 * 1024],  g_w3l[256 * 1024];

// ---------------- helpers ----------------
__device__ __forceinline__ float lrelu(float x) { return x > 0.f ? x : 0.2f * x; }
__device__ __forceinline__ float elu(float x)   { return x > 0.f ? x : expm1f(x); }

__device__ __forceinline__ void split_bf16(float x, __nv_bfloat16& h, __nv_bfloat16& l) {
    h = __float2bfloat16(x);
    l = __float2bfloat16(x - __bfloat162float(h));
}
__device__ __forceinline__ uint32_t smem_u32(const void* p) {
    uint32_t a;
    asm("{ .reg .u64 t; cvta.to.shared.u64 t, %1; cvt.u32.u64 %0, t; }" : "=r"(a) : "l"(p));
    return a;
}
__device__ __forceinline__ void cp_async16(uint32_t saddr, const void* gaddr, int srcsz) {
    asm volatile("cp.async.cg.shared.global [%0], [%1], 16, %2;"
                 :: "r"(saddr), "l"(gaddr), "r"(srcsz) : "memory");
}
__device__ __forceinline__ void mma_bf16(float* d, const uint32_t* a, const uint32_t* b) {
    asm volatile(
        "mma.sync.aligned.m16n8k16.row.col.f32.bf16.bf16.f32 "
        "{%0,%1,%2,%3}, {%4,%5,%6,%7}, {%8,%9}, {%0,%1,%2,%3};"
        : "+f"(d[0]), "+f"(d[1]), "+f"(d[2]), "+f"(d[3])
        : "r"(a[0]), "r"(a[1]), "r"(a[2]), "r"(a[3]), "r"(b[0]), "r"(b[1]));
}

// ---------------- bf16x3 mma.sync GEMM: C[M,N] = A @ Bt^T -------------------
// A given as bf16 hi/lo [M,K]; Bt as bf16 hi/lo [N,K] (weights pre-transposed).
// D = Ahi*Bhi + Ahi*Blo + Alo*Bhi  (fp32 accumulate)  ~= fp32 GEMM, err ~2^-18.
// CTA tile 128x128, BK=32, 3-stage cp.async pipeline, 8 warps (2x4), warp 64x32.
// SMEM rows padded to 40 bf16 (80B = 20 banks): fragment LDS conflict-free.
#define GEMM_BK 32
#define GEMM_STAGES 3
#define APAD 40
#define TILE_BF (128 * APAD)           // bf16 elems per (matrix x hi/lo) tile
#define STG_BF (4 * TILE_BF)           // Ahi, Alo, Bhi, Blo
#define GEMM_SMEM_TOTAL (GEMM_STAGES * STG_BF * 2)

template<int ACT>   // 0 = none, 1 = ELU
__global__ void __launch_bounds__(256, 1)
mma_gemm(const __nv_bfloat16* __restrict__ Ahi, const __nv_bfloat16* __restrict__ Alo,
         const __nv_bfloat16* __restrict__ Bhi, const __nv_bfloat16* __restrict__ Blo,
         const float* __restrict__ bias, float* __restrict__ C,
         __nv_bfloat16* __restrict__ Chi, __nv_bfloat16* __restrict__ Clo,
         int M, int N, int K)
{
    extern __shared__ char smem_raw[];
    __nv_bfloat16* smem = (__nv_bfloat16*)smem_raw;
    const int tid = threadIdx.x;
    const int lane = tid & 31;
    const int warp = tid >> 5;
    const int wm = warp & 1;         // 2 warps along M (64 rows each)
    const int wn = warp >> 1;        // 4 warps along N (32 cols each)
    const int row0 = blockIdx.y * 128;
    const int col0 = blockIdx.x * 128;
    const int qr = lane >> 2;        // groupID 0..7
    const int qc = lane & 3;         // threadID-in-group 0..3

    float acc[4][4][4];
#pragma unroll
    for (int i = 0; i < 4; i++)
#pragma unroll
        for (int j = 0; j < 4; j++)
#pragma unroll
            for (int r = 0; r < 4; r++) acc[i][j][r] = 0.f;

    const uint32_t sbase = smem_u32(smem);
    const int NC = K / GEMM_BK;

    auto load_tile = [&](int c, int s) {
        const int k0 = c * GEMM_BK;
        const uint32_t stb = sbase + s * STG_BF * 2;
#pragma unroll
        for (int t = 0; t < 8; t++) {           // 2048 16B chunks / 256 thr
            int id = t * 256 + tid;
            int sel = id >> 9;                  // 0 Ahi, 1 Alo, 2 Bhi, 3 Blo
            int wi = id & 511;
            int r = wi >> 2, q = wi & 3;
            uint32_t soff = stb + (sel * TILE_BF + r * APAD + q * 8) * 2;
            const __nv_bfloat16* g;
            int sz = 16;
            if (sel == 0)      { g = Ahi + (size_t)(row0 + r) * K + k0 + q * 8; if (row0 + r >= M) sz = 0; }
            else if (sel == 1) { g = Alo + (size_t)(row0 + r) * K + k0 + q * 8; if (row0 + r >= M) sz = 0; }
            else if (sel == 2) { g = Bhi + (size_t)(col0 + r) * K + k0 + q * 8; }
            else               { g = Blo + (size_t)(col0 + r) * K + k0 + q * 8; }
            cp_async16(soff, g, sz);
        }
        asm volatile("cp.async.commit_group;" ::: "memory");
    };

    for (int c = 0; c < GEMM_STAGES && c < NC; c++) load_tile(c, c);

    for (int c = 0; c < NC; c++) {
        const int s = c % GEMM_STAGES;
        const int lag = NC - 1 - c;
        if (lag >= 2)      asm volatile("cp.async.wait_group 2;" ::: "memory");
        else if (lag == 1) asm volatile("cp.async.wait_group 1;" ::: "memory");
        else               asm volatile("cp.async.wait_group 0;" ::: "memory");
        __syncthreads();

        const __nv_bfloat16* st = smem + s * STG_BF;
        const __nv_bfloat16* sAh = st;
        const __nv_bfloat16* sAl = st + TILE_BF;
        const __nv_bfloat16* sBh = st + 2 * TILE_BF;
        const __nv_bfloat16* sBl = st + 3 * TILE_BF;

#pragma unroll
        for (int ks = 0; ks < 2; ks++) {
            const int kb = ks * 16 + 2 * qc;
            uint32_t ah[4][4], al[4][4], bh[4][2], bl[4][2];
#pragma unroll
            for (int i = 0; i < 4; i++) {
                int m = wm * 64 + i * 16 + qr;
                const __nv_bfloat16* p = sAh + m * APAD + kb;
                ah[i][0] = *(const uint32_t*)p;
                ah[i][1] = *(const uint32_t*)(p + 8 * APAD);
                ah[i][2] = *(const uint32_t*)(p + 8);
                ah[i][3] = *(const uint32_t*)(p + 8 * APAD + 8);
                const __nv_bfloat16* q2 = sAl + m * APAD + kb;
                al[i][0] = *(const uint32_t*)q2;
                al[i][1] = *(const uint32_t*)(q2 + 8 * APAD);
                al[i][2] = *(const uint32_t*)(q2 + 8);
                al[i][3] = *(const uint32_t*)(q2 + 8 * APAD + 8);
            }
#pragma unroll
            for (int j = 0; j < 4; j++) {
                int n = wn * 32 + j * 8 + qr;
                const __nv_bfloat16* p = sBh + n * APAD + kb;
                bh[j][0] = *(const uint32_t*)p;
                bh[j][1] = *(const uint32_t*)(p + 8);
                const __nv_bfloat16* q2 = sBl + n * APAD + kb;
                bl[j][0] = *(const uint32_t*)q2;
                bl[j][1] = *(const uint32_t*)(q2 + 8);
            }
#pragma unroll
            for (int i = 0; i < 4; i++)
#pragma unroll
                for (int j = 0; j < 4; j++) {
                    mma_bf16(acc[i][j], ah[i], bh[j]);
                    mma_bf16(acc[i][j], ah[i], bl[j]);
                    mma_bf16(acc[i][j], al[i], bh[j]);
                }
        }
        __syncthreads();
        if (c + GEMM_STAGES < NC) load_tile(c + GEMM_STAGES, s);
    }

    // epilogue: d0,d1 = (row, 2qc..2qc+1); d2,d3 = (row+8, same cols)
#pragma unroll
    for (int i = 0; i < 4; i++) {
#pragma unroll
        for (int j = 0; j < 4; j++) {
            const int cc = col0 + wn * 32 + j * 8 + 2 * qc;
            float b0 = 0.f, b1 = 0.f;
            if (bias) { b0 = bias[cc]; b1 = bias[cc + 1]; }
#pragma unroll
            for (int half = 0; half < 2; half++) {
                int r = row0 + wm * 64 + i * 16 + qr + half * 8;
                if (r >= M) continue;
                float v0 = acc[i][j][half * 2 + 0] + b0;
                float v1 = acc[i][j][half * 2 + 1] + b1;
                if (ACT == 1) { v0 = elu(v0); v1 = elu(v1); }
                if (C) *(float2*)&C[(size_t)r * N + cc] = make_float2(v0, v1);
                if (Chi) {
                    __nv_bfloat16 h0, l0, h1, l1;
                    split_bf16(v0, h0, l0);
                    split_bf16(v1, h1, l1);
                    __nv_bfloat162 hp; hp.x = h0; hp.y = h1;
                    __nv_bfloat162 lp; lp.x = l0; lp.y = l1;
                    *(__nv_bfloat162*)&Chi[(size_t)r * N + cc] = hp;
                    *(__nv_bfloat162*)&Clo[(size_t)r * N + cc] = lp;
                }
            }
        }
    }
}

// ---------------- split fp32 -> bf16 hi/lo ----------------
__global__ void split_f32(const float* __restrict__ in,
                          __nv_bfloat16* __restrict__ hi, __nv_bfloat16* __restrict__ lo, int n)
{
    int i = blockIdx.x * blockDim.x + threadIdx.x;
    if (i < n) {
        __nv_bfloat16 h, l;
        split_bf16(in[i], h, l);
        hi[i] = h; lo[i] = l;
    }
}

// ---------------- weight transpose + split: out[N,K] = split(in[K,N]^T) ------
__global__ void transpose_split(const float* __restrict__ in,
                                __nv_bfloat16* __restrict__ oh, __nv_bfloat16* __restrict__ ol,
                                int K, int N)
{
    __shared__ float t[32][33];
    const int n0 = blockIdx.x * 32, k0 = blockIdx.y * 32;
    const int tx = threadIdx.x, ty = threadIdx.y;   // 32 x 8
#pragma unroll
    for (int i = 0; i < 32; i += 8)
        t[ty + i][tx] = in[(size_t)(k0 + ty + i) * N + n0 + tx];
    __syncthreads();
#pragma unroll
    for (int i = 0; i < 32; i += 8) {
        float v = t[tx][ty + i];
        __nv_bfloat16 h, l;
        split_bf16(v, h, l);
        oh[(size_t)(n0 + ty + i) * K + k0 + tx] = h;
        ol[(size_t)(n0 + ty + i) * K + k0 + tx] = l;
    }
}

// ---------------- attention score projections ----------------
template<int H>
__global__ void att_scores(const float* __restrict__ hW,
                           const float* __restrict__ a_src,
                           const float* __restrict__ a_dst,
                           int n)
{
    int warp = (blockIdx.x * blockDim.x + threadIdx.x) >> 5;
    int lane = threadIdx.x & 31;
    if (warp >= n * H) return;
    int node = warp / H, h = warp - node * H;
    const float* row = hW + (size_t)node * (H * 256) + h * 256;
    float ss = 0.f, sd = 0.f;
#pragma unroll
    for (int c = lane; c < 256; c += 32) {
        float v = row[c];
        ss = fmaf(v, a_src[h * 256 + c], ss);
        sd = fmaf(v, a_dst[h * 256 + c], sd);
    }
#pragma unroll
    for (int o = 16; o; o >>= 1) {
        ss += __shfl_xor_sync(0xFFFFFFFFu, ss, o);
        sd += __shfl_xor_sync(0xFFFFFFFFu, sd, o);
    }
    if (!lane) { g_es[node * H + h] = ss; g_ed[node * H + h] = sd; }
}

// ---------------- CSR construction ----------------
__global__ void zero_counts(int n) {
    int i = blockIdx.x * blockDim.x + threadIdx.x;
    if (i < n) g_deg[i] = 0;
    if (i < NGRAPH) g_gcnt[i] = 0;
}
__global__ void count_deg(const int* __restrict__ ei, int E) {
    int i = blockIdx.x * blockDim.x + threadIdx.x;
    if (i < E) atomicAdd(&g_deg[ei[E + i]], 1);
}
__global__ void count_graphs(const int* __restrict__ batch, int n) {
    int i = blockIdx.x * blockDim.x + threadIdx.x;
    if (i < n) atomicAdd(&g_gcnt[batch[i]], 1);
}
__global__ void scan_deg(int n) {
    __shared__ int part[1024];
    int tid = threadIdx.x;
    int per = (n + 1023) >> 10;
    int base = tid * per;
    int s = 0;
    for (int k = 0; k < per; k++) { int idx = base + k; if (idx < n) s += g_deg[idx]; }
    part[tid] = s;
    __syncthreads();
    for (int o = 1; o < 1024; o <<= 1) {
        int v = (tid >= o) ? part[tid - o] : 0;
        __syncthreads();
        part[tid] += v;
        __syncthreads();
    }
    int run = (tid == 0) ? 0 : part[tid - 1];
    for (int k = 0; k < per; k++) {
        int idx = base + k;
        if (idx < n) { g_off[idx] = run; g_cur[idx] = run; run += g_deg[idx]; }
    }
    if (tid == 0) g_off[n] = part[1023];
}
__global__ void graph_offsets() {
    if (threadIdx.x == 0) {
        int r = 0;
        for (int g = 0; g < NGRAPH; g++) { g_goff[g] = r; r += g_gcnt[g]; }
    }
}
__global__ void fill_csr(const int* __restrict__ ei, int E) {
    int i = blockIdx.x * blockDim.x + threadIdx.x;
    if (i < E) {
        int d = ei[E + i];
        int p = atomicAdd(&g_cur[d], 1);
        g_srcidx[p] = ei[i];
    }
}

// ---------------- fused GAT aggregation + bias + LayerNorm + ELU (+residual) ----
// Optionally emits bf16 hi/lo split of the output for the next GEMM.
template<int H, bool RES>
__global__ void gat_agg(const float* __restrict__ hW,
                        const float* __restrict__ bias,
                        const float* __restrict__ lng,
                        const float* __restrict__ lnb,
                        const float* __restrict__ resid,
                        float* __restrict__ out,
                        __nv_bfloat16* __restrict__ ohi,
                        __nv_bfloat16* __restrict__ olo)
{
    constexpr int CT = H * 256;
    constexpr int NT = CT / 4;
    const int i = blockIdx.x;
    const int tid = threadIdx.x;
    const int c0 = tid * 4;
    const int head = c0 >> 8;
    const int start = g_off[i], end = g_off[i + 1];

    float edv[H], selfl[H];
#pragma unroll
    for (int h = 0; h < H; h++) {
        edv[h] = g_ed[i * H + h];
        selfl[h] = lrelu(g_es[i * H + h] + edv[h]);
    }

    float mx[H];
#pragma unroll
    for (int h = 0; h < H; h++) mx[h] = selfl[h];
    for (int e = start + tid; e < end; e += NT) {
        int s = g_srcidx[e];
#pragma unroll
        for (int h = 0; h < H; h++) {
            float l = lrelu(g_es[s * H + h] + edv[h]);
            mx[h] = fmaxf(mx[h], l);
        }
    }
    __shared__ float red[NT];
#pragma unroll
    for (int h = 0; h < H; h++) {
        red[tid] = mx[h];
        __syncthreads();
        for (int o = NT / 2; o; o >>= 1) {
            if (tid < o) red[tid] = fmaxf(red[tid], red[tid + o]);
            __syncthreads();
        }
        mx[h] = red[0];
        __syncthreads();
    }

    float part[H];
#pragma unroll
    for (int h = 0; h < H; h++) part[h] = 0.f;
    for (int e = start + tid; e < end; e += NT) {
        int s = g_srcidx[e];
#pragma unroll
        for (int h = 0; h < H; h++) {
            float l = lrelu(g_es[s * H + h] + edv[h]);
            part[h] += __expf(l - mx[h]);
        }
    }
    float den[H];
#pragma unroll
    for (int h = 0; h < H; h++) {
        red[tid] = part[h];
        __syncthreads();
        for (int o = NT / 2; o; o >>= 1) {
            if (tid < o) red[tid] += red[tid + o];
            __syncthreads();
        }
        den[h] = red[0] + __expf(selfl[h] - mx[h]);
        __syncthreads();
    }

    const float m_h = mx[head];
    const float inv = 1.f / (den[head] + 1e-16f);
    const float edh = edv[head];
    float4 acc = make_float4(0.f, 0.f, 0.f, 0.f);
    for (int e = start; e < end; e++) {
        int s = g_srcidx[e];
        float l = lrelu(g_es[s * H + head] + edh);
        float a = __expf(l - m_h) * inv;
        float4 v = *(const float4*)&hW[(size_t)s * CT + c0];
        acc.x = fmaf(a, v.x, acc.x);
        acc.y = fmaf(a, v.y, acc.y);
        acc.z = fmaf(a, v.z, acc.z);
        acc.w = fmaf(a, v.w, acc.w);
    }
    {
        float a = __expf(selfl[head] - m_h) * inv;
        float4 v = *(const float4*)&hW[(size_t)i * CT + c0];
        acc.x = fmaf(a, v.x, acc.x);
        acc.y = fmaf(a, v.y, acc.y);
        acc.z = fmaf(a, v.z, acc.z);
        acc.w = fmaf(a, v.w, acc.w);
    }
    {
        float4 b = *(const float4*)&bias[c0];
        acc.x += b.x; acc.y += b.y; acc.z += b.z; acc.w += b.w;
    }

    float s1 = acc.x + acc.y + acc.z + acc.w;
    float s2 = acc.x * acc.x + acc.y * acc.y + acc.z * acc.z + acc.w * acc.w;
    red[tid] = s1; __syncthreads();
    for (int o = NT / 2; o; o >>= 1) { if (tid < o) red[tid] += red[tid + o]; __syncthreads(); }
    float S1 = red[0]; __syncthreads();
    red[tid] = s2; __syncthreads();
    for (int o = NT / 2; o; o >>= 1) { if (tid < o) red[tid] += red[tid + o]; __syncthreads(); }
    float S2 = red[0];

    float mu = S1 / (float)CT;
    float var = S2 / (float)CT - mu * mu;
    float rstd = rsqrtf(var + 1e-5f);
    float4 gv = *(const float4*)&lng[c0];
    float4 bv = *(const float4*)&lnb[c0];
    float o0 = elu((acc.x - mu) * rstd * gv.x + bv.x);
    float o1 = elu((acc.y - mu) * rstd * gv.y + bv.y);
    float o2 = elu((acc.z - mu) * rstd * gv.z + bv.z);
    float o3 = elu((acc.w - mu) * rstd * gv.w + bv.w);
    if (RES) {
        float4 rv = *(const float4*)&resid[(size_t)i * CT + c0];
        o0 += rv.x; o1 += rv.y; o2 += rv.z; o3 += rv.w;
    }
    *(float4*)&out[(size_t)i * CT + c0] = make_float4(o0, o1, o2, o3);

    if (ohi) {
        __nv_bfloat16 h[4], l[4];
        split_bf16(o0, h[0], l[0]);
        split_bf16(o1, h[1], l[1]);
        split_bf16(o2, h[2], l[2]);
        split_bf16(o3, h[3], l[3]);
        __nv_bfloat162 hp0; hp0.x = h[0]; hp0.y = h[1];
        __nv_bfloat162 hp1; hp1.x = h[2]; hp1.y = h[3];
        __nv_bfloat162 lp0; lp0.x = l[0]; lp0.y = l[1];
        __nv_bfloat162 lp1; lp1.x = l[2]; lp1.y = l[3];
        *(__nv_bfloat162*)&ohi[(size_t)i * CT + c0] = hp0;
        *(__nv_bfloat162*)&ohi[(size_t)i * CT + c0 + 2] = hp1;
        *(__nv_bfloat162*)&olo[(size_t)i * CT + c0] = lp0;
        *(__nv_bfloat162*)&olo[(size_t)i * CT + c0 + 2] = lp1;
    }
}

// ---------------- per-graph pooling: mean | max | sum ----------------
__global__ void pool_kernel(const float* __restrict__ x3) {
    int g = blockIdx.x;
    int tid = threadIdx.x;
    int s = g_goff[g], cnt = g_gcnt[g];
    float sum = 0.f, mx = -INFINITY;
    for (int k = 0; k < cnt; k++) {
        float v = x3[(size_t)(s + k) * 256 + tid];
        sum += v;
        mx = fmaxf(mx, v);
    }
    float mean = sum / fmaxf((float)cnt, 1.f);
    g_pooled[g * 768 + tid] = mean;
    g_pooled[g * 768 + 256 + tid] = mx;
    g_pooled[g * 768 + 512 + tid] = sum;
}

// ---------------- classifier head ----------------
__global__ void classify(const float* __restrict__ w1, const float* __restrict__ b1,
                         const float* __restrict__ w2, const float* __restrict__ b2,
                         float* __restrict__ outv)
{
    int g = blockIdx.x;
    int j = threadIdx.x;
    float s = b1[j];
    for (int k = 0; k < 768; k++)
        s = fmaf(g_pooled[g * 768 + k], w1[k * 128 + j], s);
    s = fmaxf(s, 0.f);
    float t = s * w2[j];
    __shared__ float red[128];
    red[j] = t; __syncthreads();
    for (int o = 64; o; o >>= 1) { if (j < o) red[j] += red[j + o]; __syncthreads(); }
    if (!j) outv[g] = red[0] + b2[0];
}

// ---------------- launch ----------------
extern "C" void kernel_launch(void* const* d_in, const int* in_sizes, int n_in,
                              void* d_out, int out_size)
{
    const float* x        = (const float*)d_in[0];
    const int*   ei       = (const int*)d_in[1];
    const int*   batch    = (const int*)d_in[2];
    const float* proj_w   = (const float*)d_in[3];
    const float* proj_b   = (const float*)d_in[4];
    const float* gat1_w   = (const float*)d_in[5];
    const float* att1_src = (const float*)d_in[6];
    const float* att1_dst = (const float*)d_in[7];
    const float* gat1_b   = (const float*)d_in[8];
    const float* ln1_g    = (const float*)d_in[9];
    const float* ln1_b    = (const float*)d_in[10];
    const float* gat2_w   = (const float*)d_in[11];
    const float* att2_src = (const float*)d_in[12];
    const float* att2_dst = (const float*)d_in[13];
    const float* gat2_b   = (const float*)d_in[14];
    const float* ln2_g    = (const float*)d_in[15];
    const float* ln2_b    = (const float*)d_in[16];
    const float* gat3_w   = (const float*)d_in[17];
    const float* att3_src = (const float*)d_in[18];
    const float* att3_dst = (const float*)d_in[19];
    const float* gat3_b   = (const float*)d_in[20];
    const float* ln3_g    = (const float*)d_in[21];
    const float* ln3_b    = (const float*)d_in[22];
    const float* cls1_w   = (const float*)d_in[23];
    const float* cls1_b   = (const float*)d_in[24];
    const float* cls2_w   = (const float*)d_in[25];
    const float* cls2_b   = (const float*)d_in[26];

    const int N = in_sizes[0] / 768;
    const int E = in_sizes[1] / 2;
    const int G = out_size;

    float* bufA; cudaGetSymbolAddress((void**)&bufA, g_bufA);
    float* bufB; cudaGetSymbolAddress((void**)&bufB, g_bufB);
    float* bufC; cudaGetSymbolAddress((void**)&bufC, g_bufC);
    __nv_bfloat16 *h0, *l0, *h1, *l1;
    cudaGetSymbolAddress((void**)&h0, g_h0); cudaGetSymbolAddress((void**)&l0, g_l0);
    cudaGetSymbolAddress((void**)&h1, g_h1); cudaGetSymbolAddress((void**)&l1, g_l1);
    __nv_bfloat16 *wPh, *wPl, *w1h, *w1l, *w2h, *w2l, *w3h, *w3l;
    cudaGetSymbolAddress((void**)&wPh, g_wPh); cudaGetSymbolAddress((void**)&wPl, g_wPl);
    cudaGetSymbolAddress((void**)&w1h, g_w1h); cudaGetSymbolAddress((void**)&w1l, g_w1l);
    cudaGetSymbolAddress((void**)&w2h, g_w2h); cudaGetSymbolAddress((void**)&w2l, g_w2l);
    cudaGetSymbolAddress((void**)&w3h, g_w3h); cudaGetSymbolAddress((void**)&w3l, g_w3l);

    cudaFuncSetAttribute(mma_gemm<0>, cudaFuncAttributeMaxDynamicSharedMemorySize, GEMM_SMEM_TOTAL);
    cudaFuncSetAttribute(mma_gemm<1>, cudaFuncAttributeMaxDynamicSharedMemorySize, GEMM_SMEM_TOTAL);

    // CSR + graph segmentation
    zero_counts<<<(N + 255) / 256, 256>>>(N);
    count_deg<<<(E + 255) / 256, 256>>>(ei, E);
    count_graphs<<<(N + 255) / 256, 256>>>(batch, N);
    scan_deg<<<1, 1024>>>(N);
    graph_offsets<<<1, 32>>>();
    fill_csr<<<(E + 255) / 256, 256>>>(ei, E);

    // operand preparation: split x, transpose+split weights
    split_f32<<<(N * 768 + 255) / 256, 256>>>(x, h1, l1, N * 768);
    dim3 tb(32, 8);
    transpose_split<<<dim3(768 / 32, 768 / 32), tb>>>(proj_w, wPh, wPl, 768, 768);
    transpose_split<<<dim3(1024 / 32, 768 / 32), tb>>>(gat1_w, w1h, w1l, 768, 1024);
    transpose_split<<<dim3(1024 / 32, 1024 / 32), tb>>>(gat2_w, w2h, w2l, 1024, 1024);
    transpose_split<<<dim3(256 / 32, 1024 / 32), tb>>>(gat3_w, w3h, w3l, 1024, 256);

    const int MT = (N + 127) / 128;

    // proj: h = elu(x @ proj_w + b) -> hi/lo slot0 only (feeds gemm1)
    mma_gemm<1><<<dim3(768 / 128, MT), 256, GEMM_SMEM_TOTAL>>>(
        h1, l1, wPh, wPl, proj_b, nullptr, h0, l0, N, 768, 768);

    // ---- GAT layer 1 ----
    mma_gemm<0><<<dim3(1024 / 128, MT), 256, GEMM_SMEM_TOTAL>>>(
        h0, l0, w1h, w1l, nullptr, bufB, nullptr, nullptr, N, 1024, 768);
    att_scores<4><<<(N * 4 + 7) / 8, 256>>>(bufB, att1_src, att1_dst, N);
    gat_agg<4, false><<<N, 256>>>(bufB, gat1_b, ln1_g, ln1_b, nullptr, bufC, h1, l1);   // bufC = x1

    // ---- GAT layer 2 ----
    mma_gemm<0><<<dim3(1024 / 128, MT), 256, GEMM_SMEM_TOTAL>>>(
        h1, l1, w2h, w2l, nullptr, bufB, nullptr, nullptr, N, 1024, 1024);
    att_scores<4><<<(N * 4 + 7) / 8, 256>>>(bufB, att2_src, att2_dst, N);
    gat_agg<4, true><<<N, 256>>>(bufB, gat2_b, ln2_g, ln2_b, bufC, bufA, h0, l0);       // x2 -> slot0

    // ---- GAT layer 3 ----
    mma_gemm<0><<<dim3(256 / 128, MT), 256, GEMM_SMEM_TOTAL>>>(
        h0, l0, w3h, w3l, nullptr, bufB, nullptr, nullptr, N, 256, 1024);
    att_scores<1><<<(N + 7) / 8, 256>>>(bufB, att3_src, att3_dst, N);
    gat_agg<1, false><<<N, 64>>>(bufB, gat3_b, ln3_g, ln3_b, nullptr, bufC, nullptr, nullptr); // x3

    // ---- pooling + classifier ----
    pool_kernel<<<G, 256>>>(bufC);
    classify<<<G, 128>>>(cls1_w, cls1_b, cls2_w, cls2_b, (float*)d_out);
}